// round 14
// baseline (speedup 1.0000x reference)
#include <cuda_runtime.h>
#include <cuda_fp16.h>
#include <cstdint>
#include <math.h>

// ---------------- problem constants ----------------
static constexpr int BATCH  = 64;
static constexpr int NA     = 8192;                  // i dimension (mask rows, GEMM K)
static constexpr int NB     = 8192;                  // j dimension (mask cols, GEMM N)
static constexpr int NJT    = 64;                    // j tiles of 128
static constexpr int NKC    = 64;                    // k chunks of 128
static constexpr int NCHUNK = NJT * NKC;             // 4096
static constexpr int NCTA   = 148;                   // persistent grid = #SMs
static constexpr int NTHREADS = 512;                 // 16 warps = 4/SMSP

// SMEM tiles, padded pitch 136 halves = 272 B (17 x 16B -> conflict-free LDSM)
static constexpr int PITCH_B  = 272;
static constexpr int TILE_BYTES = 128 * PITCH_B;     // 34816
static constexpr int STAGE    = 2 * TILE_BYTES;      // A + B = 69632
static constexpr int ACC_OFF  = 2 * STAGE;           // 139264
static constexpr int SMEM_BYTES = ACC_OFF + 1024;
static constexpr int CB_PITCH = 132;                 // floats

// ---------------- device scratch ----------------
__device__ __half g_A[2 * BATCH * NA];   // rows 0..63 = cos(a), 64..127 = sin(a); K-major
__device__ float  g_cb[BATCH * NB];
__device__ float  g_sb[BATCH * NB];
__device__ float  g_real[BATCH];
__device__ float  g_imag[BATCH];
__device__ unsigned int g_npairs;

// ---------------- helpers ----------------
__device__ __forceinline__ uint32_t smem_u32(const void* p) {
    uint32_t a;
    asm("{ .reg .u64 t; cvta.to.shared.u64 t, %1; cvt.u32.u64 %0, t; }" : "=r"(a) : "l"(p));
    return a;
}
__device__ __forceinline__ void cp_async16(uint32_t s, const void* g) {
    asm volatile("cp.async.cg.shared.global [%0], [%1], 16;" :: "r"(s), "l"(g) : "memory");
}
#define CP_COMMIT()  asm volatile("cp.async.commit_group;" ::: "memory")
#define CP_WAIT0()   asm volatile("cp.async.wait_group 0;" ::: "memory")

#define LDSM_X4(r, addr) \
    asm volatile("ldmatrix.sync.aligned.m8n8.x4.shared.b16 {%0,%1,%2,%3}, [%4];" \
        : "=r"((r)[0]), "=r"((r)[1]), "=r"((r)[2]), "=r"((r)[3]) : "r"(addr))

#define LDSM_X4_T(r, addr) \
    asm volatile("ldmatrix.sync.aligned.m8n8.x4.trans.shared.b16 {%0,%1,%2,%3}, [%4];" \
        : "=r"((r)[0]), "=r"((r)[1]), "=r"((r)[2]), "=r"((r)[3]) : "r"(addr))

__device__ __forceinline__ void mma_16816(float* d, const uint32_t* a, const uint32_t* b) {
    asm volatile(
        "mma.sync.aligned.m16n8k16.row.col.f32.f16.f16.f32 "
        "{%0,%1,%2,%3}, {%4,%5,%6,%7}, {%8,%9}, {%0,%1,%2,%3};"
        : "+f"(d[0]), "+f"(d[1]), "+f"(d[2]), "+f"(d[3])
        : "r"(a[0]), "r"(a[1]), "r"(a[2]), "r"(a[3]), "r"(b[0]), "r"(b[1]));
}
__device__ __forceinline__ uint32_t pk(uint32_t a, uint32_t b) {  // {0,1}x2 -> half2 (exact)
    return a * 0x3C00u + b * 0x3C000000u;
}

// ---------------- prep: cos/sin + zero accumulators ----------------
__global__ void plv_prep(const float* __restrict__ pa, const float* __restrict__ pb) {
    int idx = blockIdx.x * blockDim.x + threadIdx.x;
    if (idx < BATCH * NA) {
        float s, c;
        sincosf(pa[idx], &s, &c);
        int b = idx >> 13;
        int k = idx & (NA - 1);
        g_A[(size_t)b * NA + k]        = __float2half_rn(c);
        g_A[(size_t)(b + 64) * NA + k] = __float2half_rn(s);
        sincosf(pb[idx], &s, &c);
        g_cb[idx] = c;
        g_sb[idx] = s;
    }
    if (blockIdx.x == 0) {
        if (threadIdx.x < BATCH) { g_real[threadIdx.x] = 0.0f; g_imag[threadIdx.x] = 0.0f; }
        if (threadIdx.x == BATCH) g_npairs = 0u;
    }
}

// ---------------- main: persistent fused mask-stream HMMA GEMM (512 thr) ----------------
__global__ void __launch_bounds__(NTHREADS, 1) plv_main(const int* __restrict__ mask) {
    extern __shared__ char smem_raw[];
    const uint32_t sb = smem_u32(smem_raw);

    const int tid  = threadIdx.x;
    const int wid  = tid >> 5;
    const int lane = tid & 31;
    const int wm   = wid >> 2;     // 0..3 : warp row (32 m each)
    const int wn   = wid & 3;      // 0..3 : warp col (32 n each)

    const int g0 = (int)(((long long)blockIdx.x * NCHUNK) / NCTA);
    const int g1 = (int)(((long long)(blockIdx.x + 1) * NCHUNK) / NCTA);

    float acc[2][4][4];
#pragma unroll
    for (int i = 0; i < 2; ++i)
#pragma unroll
        for (int j = 0; j < 4; ++j)
#pragma unroll
            for (int r = 0; r < 4; ++r) acc[i][j][r] = 0.0f;

    unsigned int msum = 0;

    const uint32_t lrow = (uint32_t)(lane & 15);
    const uint32_t lhi  = (uint32_t)(lane >> 4);

    // ---- A loader (cp.async, fp16 trig from gmem; L2-resident) ----
    auto load_A = [&](int g, int s) {
        const int k0 = (g & 63) * 128;
        const uint32_t dstBase = sb + (uint32_t)s * STAGE;
#pragma unroll
        for (int it = 0; it < 4; ++it) {
            const int idx = tid + it * NTHREADS;
            const int m = idx >> 4;
            const int gg = idx & 15;
            cp_async16(dstBase + (uint32_t)m * PITCH_B + (uint32_t)gg * 16,
                       (const char*)g_A + ((size_t)m * NA + (size_t)k0 + (size_t)gg * 8) * 2);
        }
        CP_COMMIT();
    };

    // ---- B loader: 8 x LDG.128 into regs (held during compute) ----
    uint4 breg[8];
    auto load_B = [&](int g) {
        const int k0 = (g & 63) * 128;
        const int j0 = (g >> 6) * 128;
        const int* base = mask + (size_t)k0 * NB + j0;
#pragma unroll
        for (int it = 0; it < 8; ++it) {
            const int idx = tid + it * NTHREADS;
            const int k = idx >> 5;
            const int n = (idx & 31) * 4;
            breg[it] = *reinterpret_cast<const uint4*>(base + (size_t)k * NB + n);
        }
    };

    // ---- B convert + STS (stage s): [k][n] fp16 ----
    auto store_B = [&](int s) {
        const uint32_t dstBase = sb + (uint32_t)s * STAGE + TILE_BYTES;
#pragma unroll
        for (int it = 0; it < 8; ++it) {
            const int idx = tid + it * NTHREADS;
            const int k = idx >> 5;
            const int n = (idx & 31) * 4;
            const uint4 v = breg[it];
            msum += v.x + v.y + v.z + v.w;
            asm volatile("st.shared.v2.b32 [%0], {%1, %2};"
                :: "r"(dstBase + (uint32_t)k * PITCH_B + (uint32_t)n * 2),
                   "r"(pk(v.x, v.y)), "r"(pk(v.z, v.w))
                : "memory");
        }
    };

    // ---- compute one chunk from stage s (warp tile 32m x 32n) ----
    auto compute = [&](int s) {
        const uint32_t aBase = sb + (uint32_t)s * STAGE + (uint32_t)(wm * 32) * PITCH_B
                             + lrow * PITCH_B + lhi * 16;
        const uint32_t bBase = sb + (uint32_t)s * STAGE + TILE_BYTES + (uint32_t)(wn * 32) * 2
                             + lrow * PITCH_B + lhi * 16;
#pragma unroll
        for (int ks = 0; ks < 8; ++ks) {
            uint32_t afr[2][4];
            LDSM_X4(afr[0], aBase + (uint32_t)ks * 32);
            LDSM_X4(afr[1], aBase + 16u * PITCH_B + (uint32_t)ks * 32);
            uint32_t bfr[2][4];
#pragma unroll
            for (int nj = 0; nj < 2; ++nj)
                LDSM_X4_T(bfr[nj], bBase + (uint32_t)ks * 16 * PITCH_B + (uint32_t)nj * 32);
#pragma unroll
            for (int mi = 0; mi < 2; ++mi)
#pragma unroll
                for (int nj = 0; nj < 2; ++nj) {
                    mma_16816(acc[mi][nj * 2 + 0], afr[mi], &bfr[nj][0]);
                    mma_16816(acc[mi][nj * 2 + 1], afr[mi], &bfr[nj][2]);
                }
        }
    };

    // ---- flush: fused cb/sb epilogue for j-tile jt, then reset acc ----
    float* cbs    = reinterpret_cast<float*>(smem_raw);            // reuses stage area
    float* sbs    = cbs + 64 * CB_PITCH;
    float* real_s = reinterpret_cast<float*>(smem_raw + ACC_OFF);
    float* imag_s = real_s + 64;
    const int tq = lane >> 2;
    const int tc = (lane & 3) * 2;

    auto flush = [&](int jt) {
        const int j0 = jt * 128;
        if (tid < 64) { real_s[tid] = 0.0f; imag_s[tid] = 0.0f; }
#pragma unroll
        for (int it = 0; it < 16; ++it) {
            const int idx = tid + it * NTHREADS;
            const int b = idx >> 7;
            const int n = idx & 127;
            cbs[b * CB_PITCH + n] = g_cb[(size_t)b * NB + j0 + n];
            sbs[b * CB_PITCH + n] = g_sb[(size_t)b * NB + j0 + n];
        }
        __syncthreads();

        const bool isCos = (wm < 2);
#pragma unroll
        for (int mi = 0; mi < 2; ++mi) {
#pragma unroll
            for (int h = 0; h < 2; ++h) {
                const int m = wm * 32 + mi * 16 + h * 8 + tq;
                const int b = m & 63;
                float racc = 0.0f, iacc = 0.0f;
#pragma unroll
                for (int ni = 0; ni < 4; ++ni) {
                    const int n = wn * 32 + ni * 8 + tc;
                    const float dlo = acc[mi][ni][h * 2 + 0];
                    const float dhi = acc[mi][ni][h * 2 + 1];
                    const float2 cv = *reinterpret_cast<const float2*>(&cbs[b * CB_PITCH + n]);
                    const float2 sv = *reinterpret_cast<const float2*>(&sbs[b * CB_PITCH + n]);
                    if (isCos) {
                        racc = fmaf(dlo, cv.x, fmaf(dhi, cv.y, racc));
                        iacc = fmaf(-dlo, sv.x, fmaf(-dhi, sv.y, iacc));
                    } else {
                        racc = fmaf(dlo, sv.x, fmaf(dhi, sv.y, racc));
                        iacc = fmaf(dlo, cv.x, fmaf(dhi, cv.y, iacc));
                    }
                }
                atomicAdd(&real_s[b], racc);
                atomicAdd(&imag_s[b], iacc);
            }
        }
        __syncthreads();
        if (tid < 64) {
            atomicAdd(&g_real[tid], real_s[tid]);
            atomicAdd(&g_imag[tid], imag_s[tid]);
        }
        __syncthreads();   // stage region free before next run's cp.async
#pragma unroll
        for (int i = 0; i < 2; ++i)
#pragma unroll
            for (int j = 0; j < 4; ++j)
#pragma unroll
                for (int r = 0; r < 4; ++r) acc[i][j][r] = 0.0f;
    };

    // ---------------- persistent chunk runs ----------------
    int g = g0;
    while (g < g1) {
        const int jt   = g >> 6;
        const int gend = min(g1, (jt + 1) * NKC);
        const int nrun = gend - g;

        load_A(g, 0);
        load_B(g);
        store_B(0);
        CP_WAIT0();
        __syncthreads();

        for (int k = 0; k < nrun; ++k) {
            const int s = k & 1;
            if (k + 1 < nrun) {
                load_B(g + k + 1);          // LDGs in flight during compute
                load_A(g + k + 1, s ^ 1);
            }
            compute(s);
            if (k + 1 < nrun) {
                store_B(s ^ 1);
                CP_WAIT0();
            }
            __syncthreads();
        }

        flush(jt);
        g = gend;
    }

    // ---- n_pairs reduce (each mask element converted exactly once globally) ----
#pragma unroll
    for (int o = 16; o; o >>= 1) msum += __shfl_down_sync(0xFFFFFFFFu, msum, o);
    if (lane == 0) atomicAdd(&g_npairs, msum);
}

// ---------------- final ----------------
__global__ void plv_final(float* __restrict__ out) {
    const int b = threadIdx.x;
    if (b < BATCH) {
        const float np = fmaxf((float)g_npairs, 1.0f);
        const float r = g_real[b], i = g_imag[b];
        out[b] = sqrtf(r * r + i * i) / np;
    }
}

// ---------------- launch ----------------
extern "C" void kernel_launch(void* const* d_in, const int* in_sizes, int n_in,
                              void* d_out, int out_size) {
    (void)in_sizes; (void)n_in; (void)out_size;
    const float* pa = (const float*)d_in[0];
    const float* pb = (const float*)d_in[1];
    const int* mask = (const int*)d_in[2];
    float* out      = (float*)d_out;

    cudaFuncSetAttribute(plv_main, cudaFuncAttributeMaxDynamicSharedMemorySize, SMEM_BYTES);

    plv_prep<<<(BATCH * NA + 255) / 256, 256>>>(pa, pb);
    plv_main<<<NCTA, NTHREADS, SMEM_BYTES>>>(mask);
    plv_final<<<1, 64>>>(out);
}

// round 15
// speedup vs baseline: 1.0096x; 1.0096x over previous
#include <cuda_runtime.h>
#include <cuda_fp16.h>
#include <cstdint>
#include <math.h>

// ---------------- problem constants ----------------
static constexpr int BATCH  = 64;
static constexpr int NA     = 8192;                  // i dimension (mask rows, GEMM K)
static constexpr int NB     = 8192;                  // j dimension (mask cols, GEMM N)
static constexpr int NJT    = 64;                    // j tiles of 128
static constexpr int NKC    = 64;                    // k chunks of 128
static constexpr int NCHUNK = NJT * NKC;             // 4096
static constexpr int NCTA   = 148;                   // persistent grid = #SMs
static constexpr int NTHREADS = 256;                 // 8 warps = 2/SMSP (R12 showed more is worse)

// SMEM tiles, padded pitch 136 halves = 272 B (17 x 16B -> conflict-free LDSM)
static constexpr int PITCH_B  = 272;
static constexpr int TILE_BYTES = 128 * PITCH_B;     // 34816
static constexpr int STAGE    = 2 * TILE_BYTES;      // A + B = 69632
static constexpr int ACC_OFF  = 2 * STAGE;           // 139264
static constexpr int SMEM_BYTES = ACC_OFF + 1024;
static constexpr int CB_PITCH = 132;                 // floats

// ---------------- device scratch ----------------
__device__ __half g_A[2 * BATCH * NA];   // rows 0..63 = cos(a), 64..127 = sin(a); K-major
__device__ float  g_cb[BATCH * NB];
__device__ float  g_sb[BATCH * NB];
__device__ float  g_real[BATCH];
__device__ float  g_imag[BATCH];
__device__ unsigned int g_npairs;

// ---------------- helpers ----------------
__device__ __forceinline__ uint32_t smem_u32(const void* p) {
    uint32_t a;
    asm("{ .reg .u64 t; cvta.to.shared.u64 t, %1; cvt.u32.u64 %0, t; }" : "=r"(a) : "l"(p));
    return a;
}
__device__ __forceinline__ void cp_async16(uint32_t s, const void* g) {
    asm volatile("cp.async.cg.shared.global [%0], [%1], 16;" :: "r"(s), "l"(g) : "memory");
}
#define CP_COMMIT()  asm volatile("cp.async.commit_group;" ::: "memory")
#define CP_WAIT0()   asm volatile("cp.async.wait_group 0;" ::: "memory")

#define LDSM_X4(r, addr) \
    asm volatile("ldmatrix.sync.aligned.m8n8.x4.shared.b16 {%0,%1,%2,%3}, [%4];" \
        : "=r"((r)[0]), "=r"((r)[1]), "=r"((r)[2]), "=r"((r)[3]) : "r"(addr))

#define LDSM_X4_T(r, addr) \
    asm volatile("ldmatrix.sync.aligned.m8n8.x4.trans.shared.b16 {%0,%1,%2,%3}, [%4];" \
        : "=r"((r)[0]), "=r"((r)[1]), "=r"((r)[2]), "=r"((r)[3]) : "r"(addr))

__device__ __forceinline__ void mma_16816(float* d, const uint32_t* a, const uint32_t* b) {
    asm volatile(
        "mma.sync.aligned.m16n8k16.row.col.f32.f16.f16.f32 "
        "{%0,%1,%2,%3}, {%4,%5,%6,%7}, {%8,%9}, {%0,%1,%2,%3};"
        : "+f"(d[0]), "+f"(d[1]), "+f"(d[2]), "+f"(d[3])
        : "r"(a[0]), "r"(a[1]), "r"(a[2]), "r"(a[3]), "r"(b[0]), "r"(b[1]));
}
__device__ __forceinline__ uint32_t pk(uint32_t a, uint32_t b) {  // {0,1}x2 -> half2 (exact)
    return a * 0x3C00u + b * 0x3C000000u;
}

// ---------------- prep: fast cos/sin (MUFU) + zero accumulators ----------------
__global__ void plv_prep(const float* __restrict__ pa, const float* __restrict__ pb) {
    int idx = blockIdx.x * blockDim.x + threadIdx.x;
    if (idx < BATCH * NA) {
        float s, c;
        __sincosf(pa[idx], &s, &c);
        int b = idx >> 13;
        int k = idx & (NA - 1);
        g_A[(size_t)b * NA + k]        = __float2half_rn(c);
        g_A[(size_t)(b + 64) * NA + k] = __float2half_rn(s);
        __sincosf(pb[idx], &s, &c);
        g_cb[idx] = c;
        g_sb[idx] = s;
    }
    if (blockIdx.x == 0) {
        if (threadIdx.x < BATCH) { g_real[threadIdx.x] = 0.0f; g_imag[threadIdx.x] = 0.0f; }
        if (threadIdx.x == BATCH) g_npairs = 0u;
    }
}

// ---------------- main: persistent fused mask-stream HMMA GEMM ----------------
__global__ void __launch_bounds__(NTHREADS, 1) plv_main(const int* __restrict__ mask) {
    extern __shared__ char smem_raw[];
    const uint32_t sb = smem_u32(smem_raw);

    const int tid  = threadIdx.x;
    const int wid  = tid >> 5;
    const int lane = tid & 31;
    const int wm   = wid >> 1;     // 0..3 : warp row (32 m each)
    const int wn   = wid & 1;      // 0..1 : warp col (64 n each)

    const int g0 = (int)(((long long)blockIdx.x * NCHUNK) / NCTA);
    const int g1 = (int)(((long long)(blockIdx.x + 1) * NCHUNK) / NCTA);

    float acc[2][8][4];
#pragma unroll
    for (int i = 0; i < 2; ++i)
#pragma unroll
        for (int j = 0; j < 8; ++j)
#pragma unroll
            for (int r = 0; r < 4; ++r) acc[i][j][r] = 0.0f;

    unsigned int msum = 0;

    const uint32_t lrow = (uint32_t)(lane & 15);
    const uint32_t lhi  = (uint32_t)(lane >> 4);

    // ---- A loader (cp.async, fp16 trig straight from gmem) ----
    auto load_A = [&](int g, int s) {
        const int k0 = (g & 63) * 128;
        const uint32_t dstBase = sb + (uint32_t)s * STAGE;
#pragma unroll
        for (int it = 0; it < 8; ++it) {
            const int idx = tid + it * 256;
            const int m = idx >> 4;
            const int gg = idx & 15;
            cp_async16(dstBase + (uint32_t)m * PITCH_B + (uint32_t)gg * 16,
                       (const char*)g_A + ((size_t)m * NA + (size_t)k0 + (size_t)gg * 8) * 2);
        }
        CP_COMMIT();
    };

    // ---- B loader: 16 x LDG.128 into regs (2 adjacent per (k, n16) task) ----
    uint4 breg[16];
    auto load_B = [&](int g) {
        const int k0 = (g & 63) * 128;
        const int j0 = (g >> 6) * 128;
        const int* base = mask + (size_t)k0 * NB + j0;
#pragma unroll
        for (int it = 0; it < 8; ++it) {
            const int idx = tid + it * 256;          // 0..2047
            const int k   = idx >> 4;                // 0..127
            const int n16 = idx & 15;                // 16B-output group: 8 n-values
            const int* p  = base + (size_t)k * NB + n16 * 8;
            breg[it * 2 + 0] = *reinterpret_cast<const uint4*>(p);
            breg[it * 2 + 1] = *reinterpret_cast<const uint4*>(p + 4);
        }
    };

    // ---- B convert + STS (stage s): [k][n] fp16, 16B/thread -> conflict-free ----
    auto store_B = [&](int s) {
        const uint32_t dstBase = sb + (uint32_t)s * STAGE + TILE_BYTES;
#pragma unroll
        for (int it = 0; it < 8; ++it) {
            const int idx = tid + it * 256;
            const int k   = idx >> 4;
            const int n16 = idx & 15;
            const uint4 v0 = breg[it * 2 + 0];
            const uint4 v1 = breg[it * 2 + 1];
            msum += v0.x + v0.y + v0.z + v0.w + v1.x + v1.y + v1.z + v1.w;
            asm volatile("st.shared.v4.b32 [%0], {%1, %2, %3, %4};"
                :: "r"(dstBase + (uint32_t)k * PITCH_B + (uint32_t)n16 * 16),
                   "r"(pk(v0.x, v0.y)), "r"(pk(v0.z, v0.w)),
                   "r"(pk(v1.x, v1.y)), "r"(pk(v1.z, v1.w))
                : "memory");
        }
    };

    // ---- compute one chunk from stage s (warp tile 32m x 64n) ----
    auto compute = [&](int s) {
        const uint32_t aBase = sb + (uint32_t)s * STAGE + (uint32_t)(wm * 32) * PITCH_B
                             + lrow * PITCH_B + lhi * 16;
        const uint32_t bBase = sb + (uint32_t)s * STAGE + TILE_BYTES + (uint32_t)(wn * 64) * 2
                             + lrow * PITCH_B + lhi * 16;
#pragma unroll
        for (int ks = 0; ks < 8; ++ks) {
            uint32_t afr[2][4];
            LDSM_X4(afr[0], aBase + (uint32_t)ks * 32);
            LDSM_X4(afr[1], aBase + 16u * PITCH_B + (uint32_t)ks * 32);
            uint32_t bfr[4][4];
#pragma unroll
            for (int nj = 0; nj < 4; ++nj)
                LDSM_X4_T(bfr[nj], bBase + (uint32_t)ks * 16 * PITCH_B + (uint32_t)nj * 32);
#pragma unroll
            for (int mi = 0; mi < 2; ++mi)
#pragma unroll
                for (int nj = 0; nj < 4; ++nj) {
                    mma_16816(acc[mi][nj * 2 + 0], afr[mi], &bfr[nj][0]);
                    mma_16816(acc[mi][nj * 2 + 1], afr[mi], &bfr[nj][2]);
                }
        }
    };

    // ---- flush: fused cb/sb epilogue for j-tile jt, then reset acc ----
    float* cbs    = reinterpret_cast<float*>(smem_raw);            // reuses stage area
    float* sbs    = cbs + 64 * CB_PITCH;
    float* real_s = reinterpret_cast<float*>(smem_raw + ACC_OFF);
    float* imag_s = real_s + 64;
    const int tq = lane >> 2;
    const int tc = (lane & 3) * 2;

    auto flush = [&](int jt) {
        const int j0 = jt * 128;
        if (tid < 64) { real_s[tid] = 0.0f; imag_s[tid] = 0.0f; }
#pragma unroll
        for (int it = 0; it < 32; ++it) {
            const int idx = tid + it * 256;
            const int b = idx >> 7;
            const int n = idx & 127;
            cbs[b * CB_PITCH + n] = g_cb[(size_t)b * NB + j0 + n];
            sbs[b * CB_PITCH + n] = g_sb[(size_t)b * NB + j0 + n];
        }
        __syncthreads();

        const bool isCos = (wm < 2);
#pragma unroll
        for (int mi = 0; mi < 2; ++mi) {
#pragma unroll
            for (int h = 0; h < 2; ++h) {
                const int m = wm * 32 + mi * 16 + h * 8 + tq;
                const int b = m & 63;
                float racc = 0.0f, iacc = 0.0f;
#pragma unroll
                for (int ni = 0; ni < 8; ++ni) {
                    const int n = wn * 64 + ni * 8 + tc;
                    const float dlo = acc[mi][ni][h * 2 + 0];
                    const float dhi = acc[mi][ni][h * 2 + 1];
                    const float2 cv = *reinterpret_cast<const float2*>(&cbs[b * CB_PITCH + n]);
                    const float2 sv = *reinterpret_cast<const float2*>(&sbs[b * CB_PITCH + n]);
                    if (isCos) {
                        racc = fmaf(dlo, cv.x, fmaf(dhi, cv.y, racc));
                        iacc = fmaf(-dlo, sv.x, fmaf(-dhi, sv.y, iacc));
                    } else {
                        racc = fmaf(dlo, sv.x, fmaf(dhi, sv.y, racc));
                        iacc = fmaf(dlo, cv.x, fmaf(dhi, cv.y, iacc));
                    }
                }
                atomicAdd(&real_s[b], racc);
                atomicAdd(&imag_s[b], iacc);
            }
        }
        __syncthreads();
        if (tid < 64) {
            atomicAdd(&g_real[tid], real_s[tid]);
            atomicAdd(&g_imag[tid], imag_s[tid]);
        }
        __syncthreads();   // stage region free before next run's cp.async
#pragma unroll
        for (int i = 0; i < 2; ++i)
#pragma unroll
            for (int j = 0; j < 8; ++j)
#pragma unroll
                for (int r = 0; r < 4; ++r) acc[i][j][r] = 0.0f;
    };

    // ---------------- persistent chunk runs ----------------
    int g = g0;
    while (g < g1) {
        const int jt   = g >> 6;
        const int gend = min(g1, (jt + 1) * NKC);
        const int nrun = gend - g;

        load_A(g, 0);
        load_B(g);
        store_B(0);
        CP_WAIT0();
        __syncthreads();

        for (int k = 0; k < nrun; ++k) {
            const int s = k & 1;
            if (k + 1 < nrun) {
                load_B(g + k + 1);          // LDGs in flight during compute
                load_A(g + k + 1, s ^ 1);
            }
            compute(s);
            if (k + 1 < nrun) {
                store_B(s ^ 1);
                CP_WAIT0();
            }
            __syncthreads();
        }

        flush(jt);
        g = gend;
    }

    // ---- n_pairs reduce (each mask element converted exactly once globally) ----
#pragma unroll
    for (int o = 16; o; o >>= 1) msum += __shfl_down_sync(0xFFFFFFFFu, msum, o);
    if (lane == 0) atomicAdd(&g_npairs, msum);
}

// ---------------- final ----------------
__global__ void plv_final(float* __restrict__ out) {
    const int b = threadIdx.x;
    if (b < BATCH) {
        const float np = fmaxf((float)g_npairs, 1.0f);
        const float r = g_real[b], i = g_imag[b];
        out[b] = sqrtf(r * r + i * i) / np;
    }
}

// ---------------- launch ----------------
extern "C" void kernel_launch(void* const* d_in, const int* in_sizes, int n_in,
                              void* d_out, int out_size) {
    (void)in_sizes; (void)n_in; (void)out_size;
    const float* pa = (const float*)d_in[0];
    const float* pb = (const float*)d_in[1];
    const int* mask = (const int*)d_in[2];
    float* out      = (float*)d_out;

    cudaFuncSetAttribute(plv_main, cudaFuncAttributeMaxDynamicSharedMemorySize, SMEM_BYTES);

    plv_prep<<<(BATCH * NA + 255) / 256, 256>>>(pa, pb);
    plv_main<<<NCTA, NTHREADS, SMEM_BYTES>>>(mask);
    plv_final<<<1, 64>>>(out);
}

// round 16
// speedup vs baseline: 1.0389x; 1.0290x over previous
#include <cuda_runtime.h>
#include <cuda_fp16.h>
#include <cstdint>
#include <math.h>

// ---------------- problem constants ----------------
static constexpr int BATCH  = 64;
static constexpr int NA     = 8192;                  // i dimension (mask rows, GEMM K)
static constexpr int NB     = 8192;                  // j dimension (mask cols, GEMM N)
static constexpr int NJT    = 64;                    // j tiles of 128
static constexpr int NKC    = 64;                    // k chunks of 128
static constexpr int NCHUNK = NJT * NKC;             // 4096
static constexpr int NCTA   = 148;                   // persistent grid = #SMs
static constexpr int NTHREADS = 256;                 // 8 warps = 2/SMSP

// SMEM tiles, padded pitch 136 halves = 272 B (17 x 16B -> conflict-free LDSM)
static constexpr int PITCH_B  = 272;
static constexpr int TILE_BYTES = 128 * PITCH_B;     // 34816
static constexpr int STAGE    = 2 * TILE_BYTES;      // A + B = 69632
static constexpr int ACC_OFF  = 2 * STAGE;           // 139264
static constexpr int SMEM_BYTES = ACC_OFF + 1024;
static constexpr int CB_PITCH = 132;                 // floats

// ---------------- device scratch ----------------
__device__ __half g_A[2 * BATCH * NA];   // rows 0..63 = cos(a), 64..127 = sin(a); K-major
__device__ float  g_cb[BATCH * NB];
__device__ float  g_sb[BATCH * NB];
__device__ float  g_real[BATCH];
__device__ float  g_imag[BATCH];
__device__ unsigned int g_npairs;

// ---------------- helpers ----------------
__device__ __forceinline__ uint32_t smem_u32(const void* p) {
    uint32_t a;
    asm("{ .reg .u64 t; cvta.to.shared.u64 t, %1; cvt.u32.u64 %0, t; }" : "=r"(a) : "l"(p));
    return a;
}
__device__ __forceinline__ void cp_async16(uint32_t s, const void* g) {
    asm volatile("cp.async.cg.shared.global [%0], [%1], 16;" :: "r"(s), "l"(g) : "memory");
}
#define CP_COMMIT()  asm volatile("cp.async.commit_group;" ::: "memory")
#define CP_WAIT0()   asm volatile("cp.async.wait_group 0;" ::: "memory")

#define LDSM_X4(r, addr) \
    asm volatile("ldmatrix.sync.aligned.m8n8.x4.shared.b16 {%0,%1,%2,%3}, [%4];" \
        : "=r"((r)[0]), "=r"((r)[1]), "=r"((r)[2]), "=r"((r)[3]) : "r"(addr))

#define LDSM_X4_T(r, addr) \
    asm volatile("ldmatrix.sync.aligned.m8n8.x4.trans.shared.b16 {%0,%1,%2,%3}, [%4];" \
        : "=r"((r)[0]), "=r"((r)[1]), "=r"((r)[2]), "=r"((r)[3]) : "r"(addr))

// fp16-accumulator legacy HMMA: D(f16x4 in 2 regs) = A*B + C
__device__ __forceinline__ void mma_16816_h(uint32_t* d, const uint32_t* a, const uint32_t* b) {
    asm volatile(
        "mma.sync.aligned.m16n8k16.row.col.f16.f16.f16.f16 "
        "{%0,%1}, {%2,%3,%4,%5}, {%6,%7}, {%0,%1};"
        : "+r"(d[0]), "+r"(d[1])
        : "r"(a[0]), "r"(a[1]), "r"(a[2]), "r"(a[3]), "r"(b[0]), "r"(b[1]));
}
__device__ __forceinline__ uint32_t pk(uint32_t a, uint32_t b) {  // {0,1}x2 -> half2 (exact)
    return a * 0x3C00u + b * 0x3C000000u;
}

// ---------------- prep: fast cos/sin (MUFU, validated R14) + zero accumulators ----------------
__global__ void plv_prep(const float* __restrict__ pa, const float* __restrict__ pb) {
    int idx = blockIdx.x * blockDim.x + threadIdx.x;
    if (idx < BATCH * NA) {
        float s, c;
        __sincosf(pa[idx], &s, &c);
        int b = idx >> 13;
        int k = idx & (NA - 1);
        g_A[(size_t)b * NA + k]        = __float2half_rn(c);
        g_A[(size_t)(b + 64) * NA + k] = __float2half_rn(s);
        __sincosf(pb[idx], &s, &c);
        g_cb[idx] = c;
        g_sb[idx] = s;
    }
    if (blockIdx.x == 0) {
        if (threadIdx.x < BATCH) { g_real[threadIdx.x] = 0.0f; g_imag[threadIdx.x] = 0.0f; }
        if (threadIdx.x == BATCH) g_npairs = 0u;
    }
}

// ---------------- main: persistent fused mask-stream HMMA GEMM (fp16 accum) ----------------
__global__ void __launch_bounds__(NTHREADS, 1) plv_main(const int* __restrict__ mask) {
    extern __shared__ char smem_raw[];
    const uint32_t sb = smem_u32(smem_raw);

    const int tid  = threadIdx.x;
    const int wid  = tid >> 5;
    const int lane = tid & 31;
    const int wm   = wid >> 1;     // 0..3 : warp row (32 m each)
    const int wn   = wid & 1;      // 0..1 : warp col (64 n each)

    const int g0 = (int)(((long long)blockIdx.x * NCHUNK) / NCTA);
    const int g1 = (int)(((long long)(blockIdx.x + 1) * NCHUNK) / NCTA);

    float    acc[2][8][4];      // f32 shadow (promoted per chunk)
    uint32_t acch[2][8][2];     // fp16 accumulators (one chunk's partial)
#pragma unroll
    for (int i = 0; i < 2; ++i)
#pragma unroll
        for (int j = 0; j < 8; ++j) {
#pragma unroll
            for (int r = 0; r < 4; ++r) acc[i][j][r] = 0.0f;
            acch[i][j][0] = 0u; acch[i][j][1] = 0u;
        }

    unsigned int msum = 0;

    const uint32_t lrow = (uint32_t)(lane & 15);
    const uint32_t lhi  = (uint32_t)(lane >> 4);

    // ---- A loader (cp.async, fp16 trig straight from gmem) ----
    auto load_A = [&](int g, int s) {
        const int k0 = (g & 63) * 128;
        const uint32_t dstBase = sb + (uint32_t)s * STAGE;
#pragma unroll
        for (int it = 0; it < 8; ++it) {
            const int idx = tid + it * 256;
            const int m = idx >> 4;
            const int gg = idx & 15;
            cp_async16(dstBase + (uint32_t)m * PITCH_B + (uint32_t)gg * 16,
                       (const char*)g_A + ((size_t)m * NA + (size_t)k0 + (size_t)gg * 8) * 2);
        }
        CP_COMMIT();
    };

    // ---- B loader: 16 x LDG.128 into regs (R11-exact) ----
    uint4 breg[16];
    auto load_B = [&](int g) {
        const int k0 = (g & 63) * 128;
        const int j0 = (g >> 6) * 128;
        const int* base = mask + (size_t)k0 * NB + j0;
#pragma unroll
        for (int it = 0; it < 16; ++it) {
            const int idx = tid + it * 256;
            const int k = idx >> 5;
            const int n = (idx & 31) * 4;
            breg[it] = *reinterpret_cast<const uint4*>(base + (size_t)k * NB + n);
        }
    };

    // ---- B convert + STS (stage s): [k][n] fp16 (R11-exact) ----
    auto store_B = [&](int s) {
        const uint32_t dstBase = sb + (uint32_t)s * STAGE + TILE_BYTES;
#pragma unroll
        for (int it = 0; it < 16; ++it) {
            const int idx = tid + it * 256;
            const int k = idx >> 5;
            const int n = (idx & 31) * 4;
            const uint4 v = breg[it];
            msum += v.x + v.y + v.z + v.w;
            asm volatile("st.shared.v2.b32 [%0], {%1, %2};"
                :: "r"(dstBase + (uint32_t)k * PITCH_B + (uint32_t)n * 2),
                   "r"(pk(v.x, v.y)), "r"(pk(v.z, v.w))
                : "memory");
        }
    };

    // ---- compute one chunk (fp16 accum), then promote into f32 shadows ----
    auto compute = [&](int s) {
        const uint32_t aBase = sb + (uint32_t)s * STAGE + (uint32_t)(wm * 32) * PITCH_B
                             + lrow * PITCH_B + lhi * 16;
        const uint32_t bBase = sb + (uint32_t)s * STAGE + TILE_BYTES + (uint32_t)(wn * 64) * 2
                             + lrow * PITCH_B + lhi * 16;
#pragma unroll
        for (int ks = 0; ks < 8; ++ks) {
            uint32_t afr[2][4];
            LDSM_X4(afr[0], aBase + (uint32_t)ks * 32);
            LDSM_X4(afr[1], aBase + 16u * PITCH_B + (uint32_t)ks * 32);
            uint32_t bfr[4][4];
#pragma unroll
            for (int nj = 0; nj < 4; ++nj)
                LDSM_X4_T(bfr[nj], bBase + (uint32_t)ks * 16 * PITCH_B + (uint32_t)nj * 32);
#pragma unroll
            for (int mi = 0; mi < 2; ++mi)
#pragma unroll
                for (int nj = 0; nj < 4; ++nj) {
                    mma_16816_h(acch[mi][nj * 2 + 0], afr[mi], &bfr[nj][0]);
                    mma_16816_h(acch[mi][nj * 2 + 1], afr[mi], &bfr[nj][2]);
                }
        }
        // promote this chunk's fp16 partials into f32, reset fp16
#pragma unroll
        for (int mi = 0; mi < 2; ++mi)
#pragma unroll
            for (int nj = 0; nj < 8; ++nj) {
                const float2 lo = __half22float2(*reinterpret_cast<__half2*>(&acch[mi][nj][0]));
                const float2 hi = __half22float2(*reinterpret_cast<__half2*>(&acch[mi][nj][1]));
                acc[mi][nj][0] += lo.x;
                acc[mi][nj][1] += lo.y;
                acc[mi][nj][2] += hi.x;
                acc[mi][nj][3] += hi.y;
                acch[mi][nj][0] = 0u;
                acch[mi][nj][1] = 0u;
            }
    };

    // ---- flush: fused cb/sb epilogue for j-tile jt, then reset acc ----
    float* cbs    = reinterpret_cast<float*>(smem_raw);            // reuses stage area
    float* sbs    = cbs + 64 * CB_PITCH;
    float* real_s = reinterpret_cast<float*>(smem_raw + ACC_OFF);
    float* imag_s = real_s + 64;
    const int tq = lane >> 2;
    const int tc = (lane & 3) * 2;

    auto flush = [&](int jt) {
        const int j0 = jt * 128;
        if (tid < 64) { real_s[tid] = 0.0f; imag_s[tid] = 0.0f; }
#pragma unroll
        for (int it = 0; it < 32; ++it) {
            const int idx = tid + it * 256;
            const int b = idx >> 7;
            const int n = idx & 127;
            cbs[b * CB_PITCH + n] = g_cb[(size_t)b * NB + j0 + n];
            sbs[b * CB_PITCH + n] = g_sb[(size_t)b * NB + j0 + n];
        }
        __syncthreads();

        const bool isCos = (wm < 2);
#pragma unroll
        for (int mi = 0; mi < 2; ++mi) {
#pragma unroll
            for (int h = 0; h < 2; ++h) {
                const int m = wm * 32 + mi * 16 + h * 8 + tq;
                const int b = m & 63;
                float racc = 0.0f, iacc = 0.0f;
#pragma unroll
                for (int ni = 0; ni < 8; ++ni) {
                    const int n = wn * 64 + ni * 8 + tc;
                    const float dlo = acc[mi][ni][h * 2 + 0];
                    const float dhi = acc[mi][ni][h * 2 + 1];
                    const float2 cv = *reinterpret_cast<const float2*>(&cbs[b * CB_PITCH + n]);
                    const float2 sv = *reinterpret_cast<const float2*>(&sbs[b * CB_PITCH + n]);
                    if (isCos) {
                        racc = fmaf(dlo, cv.x, fmaf(dhi, cv.y, racc));
                        iacc = fmaf(-dlo, sv.x, fmaf(-dhi, sv.y, iacc));
                    } else {
                        racc = fmaf(dlo, sv.x, fmaf(dhi, sv.y, racc));
                        iacc = fmaf(dlo, cv.x, fmaf(dhi, cv.y, iacc));
                    }
                }
                atomicAdd(&real_s[b], racc);
                atomicAdd(&imag_s[b], iacc);
            }
        }
        __syncthreads();
        if (tid < 64) {
            atomicAdd(&g_real[tid], real_s[tid]);
            atomicAdd(&g_imag[tid], imag_s[tid]);
        }
        __syncthreads();   // stage region free before next run's cp.async
#pragma unroll
        for (int i = 0; i < 2; ++i)
#pragma unroll
            for (int j = 0; j < 8; ++j)
#pragma unroll
                for (int r = 0; r < 4; ++r) acc[i][j][r] = 0.0f;
    };

    // ---------------- persistent chunk runs ----------------
    int g = g0;
    while (g < g1) {
        const int jt   = g >> 6;
        const int gend = min(g1, (jt + 1) * NKC);
        const int nrun = gend - g;

        load_A(g, 0);
        load_B(g);
        store_B(0);
        CP_WAIT0();
        __syncthreads();

        for (int k = 0; k < nrun; ++k) {
            const int s = k & 1;
            if (k + 1 < nrun) {
                load_B(g + k + 1);          // LDGs in flight during compute
                load_A(g + k + 1, s ^ 1);
            }
            compute(s);
            if (k + 1 < nrun) {
                store_B(s ^ 1);
                CP_WAIT0();
            }
            __syncthreads();
        }

        flush(jt);
        g = gend;
    }

    // ---- n_pairs reduce (each mask element converted exactly once globally) ----
#pragma unroll
    for (int o = 16; o; o >>= 1) msum += __shfl_down_sync(0xFFFFFFFFu, msum, o);
    if (lane == 0) atomicAdd(&g_npairs, msum);
}

// ---------------- final ----------------
__global__ void plv_final(float* __restrict__ out) {
    const int b = threadIdx.x;
    if (b < BATCH) {
        const float np = fmaxf((float)g_npairs, 1.0f);
        const float r = g_real[b], i = g_imag[b];
        out[b] = sqrtf(r * r + i * i) / np;
    }
}

// ---------------- launch ----------------
extern "C" void kernel_launch(void* const* d_in, const int* in_sizes, int n_in,
                              void* d_out, int out_size) {
    (void)in_sizes; (void)n_in; (void)out_size;
    const float* pa = (const float*)d_in[0];
    const float* pb = (const float*)d_in[1];
    const int* mask = (const int*)d_in[2];
    float* out      = (float*)d_out;

    cudaFuncSetAttribute(plv_main, cudaFuncAttributeMaxDynamicSharedMemorySize, SMEM_BYTES);

    plv_prep<<<(BATCH * NA + 255) / 256, 256>>>(pa, pb);
    plv_main<<<NCTA, NTHREADS, SMEM_BYTES>>>(mask);
    plv_final<<<1, 64>>>(out);
}